// round 4
// baseline (speedup 1.0000x reference)
#include <cuda_runtime.h>

#define B_   128
#define T_   1024
#define IN_  128
#define H_   256
#define G3   768          // 3*H
#define NOUT 4

// ---------------------------------------------------------------------------
// Static device scratch (no cudaMalloc allowed).
// px layout: [dir][t][b][768]   (time-major so each scan step reads one slab)
// y0 layout: [t][b][512]        (row = t*128+b, K-contig for the L1 GEMM)
// ---------------------------------------------------------------------------
__device__ float    g_px0[2 * T_ * B_ * G3];          // 805 MB
__device__ float    g_px1[2 * T_ * B_ * G3];          // 805 MB
__device__ float    g_y0 [T_ * B_ * 2 * H_];          // 268 MB
__device__ float    g_h  [2 * 2 * 2 * B_ * H_];       // [layer][parity][dir][B][H]
__device__ float    g_hlast[2 * B_ * H_];             // [dir][B][H]
__device__ unsigned g_flags[2 * 2 * 8 * T_];          // [layer][dir][bgroup][step]

// ---------------------------------------------------------------------------
// Zero h buffers + sync flags (runs every launch -> graph replays deterministic)
// ---------------------------------------------------------------------------
__global__ void zero_kernel() {
    const int n1 = 2 * 2 * 2 * B_ * H_;
    const int n2 = 2 * 2 * 8 * T_;
    int stride = gridDim.x * blockDim.x;
    for (int i = blockIdx.x * blockDim.x + threadIdx.x; i < n1; i += stride)
        g_h[i] = 0.0f;
    for (int i = blockIdx.x * blockDim.x + threadIdx.x; i < n2; i += stride)
        g_flags[i] = 0u;
}

// ---------------------------------------------------------------------------
// Projection GEMM: out = A[M,K] * W[N,K]^T + bias[N], N = 1536 (2 dirs x 768)
// mode 0: A = data, row m = b*T + t   (data is [B][T][IN])
// mode 1: A = y0,   row m = t*B + b   (y0   is [T][B][2H])
// Output scattered to px[dir][t][b][g].
// Tiling: 64x64 block, BK=16, 256 threads, 4x4 per thread.
// ---------------------------------------------------------------------------
__global__ void gemm_proj(const float* __restrict__ A,
                          const float* __restrict__ W,
                          const float* __restrict__ bias,
                          float* __restrict__ out,
                          int K, int mode)
{
    __shared__ float As[16][68];
    __shared__ float Bs[16][68];

    const int tid = threadIdx.x;
    const int tx  = tid & 15;
    const int ty  = tid >> 4;
    const int m0  = blockIdx.x * 64;
    const int n0  = blockIdx.y * 64;

    float acc[4][4];
#pragma unroll
    for (int i = 0; i < 4; i++)
#pragma unroll
        for (int j = 0; j < 4; j++) acc[i][j] = 0.0f;

    for (int k0 = 0; k0 < K; k0 += 16) {
#pragma unroll
        for (int i = 0; i < 4; i++) {
            int e = tid + i * 256;          // 0..1023 over 64 rows x 16 cols
            int r = e >> 4, c = e & 15;
            As[c][r] = A[(m0 + r) * K + k0 + c];
            Bs[c][r] = W[(n0 + r) * K + k0 + c];
        }
        __syncthreads();
#pragma unroll
        for (int kk = 0; kk < 16; kk++) {
            float4 av = *(const float4*)&As[kk][ty * 4];
            float4 bv = *(const float4*)&Bs[kk][tx * 4];
            float a[4] = {av.x, av.y, av.z, av.w};
            float b[4] = {bv.x, bv.y, bv.z, bv.w};
#pragma unroll
            for (int i = 0; i < 4; i++)
#pragma unroll
                for (int j = 0; j < 4; j++)
                    acc[i][j] += a[i] * b[j];
        }
        __syncthreads();
    }

#pragma unroll
    for (int i = 0; i < 4; i++) {
        int m = m0 + ty * 4 + i;
        int t, b;
        if (mode == 0) { b = m >> 10; t = m & (T_ - 1); }
        else           { t = m >> 7;  b = m & (B_ - 1); }
#pragma unroll
        for (int j = 0; j < 4; j++) {
            int n   = n0 + tx * 4 + j;
            int dir = (n >= G3) ? 1 : 0;
            int g   = n - dir * G3;
            out[((dir * T_ + t) * B_ + b) * G3 + g] = acc[i][j] + bias[n];
        }
    }
}

// ---------------------------------------------------------------------------
// GRU scan. Grid (8 bgroups, 8 slices, 2 dirs) = 128 CTAs, 256 threads each.
// Each CTA: 16 batches x 32 hidden units, weight slice (96 rows x 256) in SMEM.
// Per step: ph = h @ Wslice^T + b_hh; gates; h_new; L2 exchange + flag sync.
// ---------------------------------------------------------------------------
#define SCAN_SMEM_FLOATS (96 * 260 + 64 * 68 + 16 * 100 + 96)
#define SCAN_SMEM_BYTES  (SCAN_SMEM_FLOATS * 4)

__global__ void gru_scan(const float* __restrict__ px,     // [2][T][B][768]
                         const float* __restrict__ w_hh,   // [2][768][256]
                         const float* __restrict__ b_hh,   // [2][768]
                         float* __restrict__ hbuf,         // [2 parity][2 dir][B][H]
                         unsigned* __restrict__ flags,     // [2 dir][8][T]
                         float* __restrict__ y_out,        // null or [T][B][2H]
                         float* __restrict__ h_last)       // null or [2][B][H]
{
    extern __shared__ float smem[];
    float* W_s  = smem;                       // [96][260] padded
    float* h_s  = W_s + 96 * 260;             // [64 kq][68] padded, 16 batches x 256 k
    float* ph_s = h_s + 64 * 68;              // [16][100]
    float* bb_s = ph_s + 16 * 100;            // [96]

    const int bg  = blockIdx.x;   // batch group 0..7   (16 batches each)
    const int sl  = blockIdx.y;   // hidden slice 0..7  (32 units each)
    const int dir = blockIdx.z;
    const int tid = threadIdx.x;

    // Load weight slice: local row lr = gate*32 + u  ->  global row gate*256 + sl*32 + u
    const float* wsrc = w_hh + dir * (G3 * H_);
    for (int e = tid; e < 96 * 256; e += 256) {
        int lr = e >> 8, k = e & 255;
        int grow = (lr >> 5) * H_ + sl * 32 + (lr & 31);
        W_s[lr * 260 + k] = wsrc[grow * H_ + k];
    }
    if (tid < 96) {
        int grow = (tid >> 5) * H_ + sl * 32 + (tid & 31);
        bb_s[tid] = b_hh[dir * G3 + grow];
    }
    __syncthreads();

    const int w     = tid >> 5;
    const int l     = tid & 31;
    const int bb    = l & 15;          // batch within group (lane-major -> coalesced h)
    const int half  = l >> 4;
    const int cbase = w * 12 + half * 6;   // 6 output rows per thread, covers 0..95

    for (int step = 0; step < T_; step++) {
        const int t = dir ? (T_ - 1 - step) : step;
        const int p = step & 1;
        const float* hsrc = hbuf + (p * 2 + dir) * (B_ * H_);
        float*       hdst = hbuf + (((p ^ 1) * 2) + dir) * (B_ * H_);

        // Load full h (16 batches x 256) into SMEM, k-major for float4 reads.
        // __ldcg: bypass (incoherent) L1 -- h was written by peer CTAs.
        for (int e = tid; e < 16 * 256; e += 256) {
            int b = e >> 8, k = e & 255;
            h_s[(k >> 2) * 68 + b * 4 + (k & 3)] = __ldcg(&hsrc[(bg * 16 + b) * H_ + k]);
        }
        __syncthreads();

        // ph[bb][cbase..cbase+5] = b_hh + sum_k h[bb][k] * W[c][k]
        float acc[6];
#pragma unroll
        for (int j = 0; j < 6; j++) acc[j] = bb_s[cbase + j];

        const float4* h4 = (const float4*)h_s;
#pragma unroll 8
        for (int kq = 0; kq < 64; kq++) {
            float4 hv = h4[kq * 17 + bb];
#pragma unroll
            for (int j = 0; j < 6; j++) {
                float4 wv = *(const float4*)&W_s[(cbase + j) * 260 + kq * 4];
                acc[j] += hv.x * wv.x;
                acc[j] += hv.y * wv.y;
                acc[j] += hv.z * wv.z;
                acc[j] += hv.w * wv.w;
            }
        }
#pragma unroll
        for (int j = 0; j < 6; j++) ph_s[bb * 100 + cbase + j] = acc[j];
        __syncthreads();

        // Gates + state update: 512 (batch,unit) tasks, 2 per thread.
#pragma unroll
        for (int it = 0; it < 2; it++) {
            int id = tid + it * 256;
            int b  = id >> 5, u = id & 31;
            int bglob = bg * 16 + b;
            int ug    = sl * 32 + u;
            const float* pxr = px + ((dir * T_ + t) * B_ + bglob) * G3;
            float xr = pxr[ug], xz = pxr[H_ + ug], xn = pxr[2 * H_ + ug];
            float hr = ph_s[b * 100 + u];
            float hz = ph_s[b * 100 + 32 + u];
            float hn = ph_s[b * 100 + 64 + u];
            float r = 1.0f / (1.0f + __expf(-(xr + hr)));
            float z = 1.0f / (1.0f + __expf(-(xz + hz)));
            float n = tanhf(xn + r * hn);
            float hp = h_s[(ug >> 2) * 68 + b * 4 + (ug & 3)];
            float hnew = (1.0f - z) * n + z * hp;
            __stcg(&hdst[bglob * H_ + ug], hnew);
            if (y_out)
                y_out[(t * B_ + bglob) * (2 * H_) + dir * H_ + ug] = hnew;
            if (h_last && step == T_ - 1)
                h_last[(dir * B_ + bglob) * H_ + ug] = hnew;
        }

        // Publish + wait for the 7 sibling slice-CTAs of this (dir, bgroup).
        __threadfence();
        __syncthreads();
        unsigned* f = flags + (dir * 8 + bg) * T_ + step;
        if (tid == 0) {
            atomicAdd(f, 1u);
            while (*(volatile unsigned*)f < 8u) { }
        }
        __syncthreads();
    }
}

// ---------------------------------------------------------------------------
// Output head: out[b][o] = concat(hf[b], hb[b]) . w_out[o] + b_out[o]
// ---------------------------------------------------------------------------
__global__ void head_kernel(const float* __restrict__ hlast,   // [2][B][H]
                            const float* __restrict__ w_out,   // [4][512]
                            const float* __restrict__ b_out,   // [4]
                            float* __restrict__ out)           // [B][4]
{
    int id = blockIdx.x * blockDim.x + threadIdx.x;
    if (id >= B_ * NOUT) return;
    int b = id >> 2, o = id & 3;
    const float* hf = hlast + b * H_;
    const float* hb = hlast + (B_ + b) * H_;
    const float* wo = w_out + o * (2 * H_);
    float s = b_out[o];
#pragma unroll 8
    for (int j = 0; j < H_; j++) s += hf[j] * wo[j];
#pragma unroll 8
    for (int j = 0; j < H_; j++) s += hb[j] * wo[H_ + j];
    out[id] = s;
}

// ---------------------------------------------------------------------------
// Launch
// ---------------------------------------------------------------------------
extern "C" void kernel_launch(void* const* d_in, const int* in_sizes, int n_in,
                              void* d_out, int out_size)
{
    const float* data  = (const float*)d_in[0];
    const float* w_ih0 = (const float*)d_in[1];
    const float* w_hh0 = (const float*)d_in[2];
    const float* b_ih0 = (const float*)d_in[3];
    const float* b_hh0 = (const float*)d_in[4];
    const float* w_ih1 = (const float*)d_in[5];
    const float* w_hh1 = (const float*)d_in[6];
    const float* b_ih1 = (const float*)d_in[7];
    const float* b_hh1 = (const float*)d_in[8];
    const float* w_out = (const float*)d_in[9];
    const float* b_out = (const float*)d_in[10];
    float* out = (float*)d_out;

    float *px0, *px1, *y0, *h, *hlast; unsigned* fl;
    cudaGetSymbolAddress((void**)&px0,   g_px0);
    cudaGetSymbolAddress((void**)&px1,   g_px1);
    cudaGetSymbolAddress((void**)&y0,    g_y0);
    cudaGetSymbolAddress((void**)&h,     g_h);
    cudaGetSymbolAddress((void**)&hlast, g_hlast);
    cudaGetSymbolAddress((void**)&fl,    g_flags);

    cudaFuncSetAttribute(gru_scan, cudaFuncAttributeMaxDynamicSharedMemorySize,
                         SCAN_SMEM_BYTES);

    zero_kernel<<<256, 256>>>();

    // Layer 0 input projection: M = B*T = 131072, K = 128
    dim3 gp(131072 / 64, 1536 / 64);
    gemm_proj<<<gp, 256>>>(data, w_ih0, b_ih0, px0, IN_, 0);

    // Layer 0 bidirectional scan (writes y0)
    dim3 gs(8, 8, 2);
    const int hLayerStride = 2 * 2 * B_ * H_;
    const int fLayerStride = 2 * 8 * T_;
    gru_scan<<<gs, 256, SCAN_SMEM_BYTES>>>(px0, w_hh0, b_hh0,
                                           h, fl, y0, nullptr);

    // Layer 1 input projection: M = T*B = 131072, K = 512
    gemm_proj<<<gp, 256>>>(y0, w_ih1, b_ih1, px1, 2 * H_, 1);

    // Layer 1 bidirectional scan (writes h_last only)
    gru_scan<<<gs, 256, SCAN_SMEM_BYTES>>>(px1, w_hh1, b_hh1,
                                           h + hLayerStride, fl + fLayerStride,
                                           nullptr, hlast);

    // Output head
    head_kernel<<<2, 256>>>(hlast, w_out, b_out, out);
}

// round 5
// speedup vs baseline: 1.1240x; 1.1240x over previous
#include <cuda_runtime.h>

#define B_   128
#define T_   1024
#define IN_  128
#define H_   256
#define G3   768          // 3*H
#define NOUT 4

// ---------------------------------------------------------------------------
// Static device scratch (no cudaMalloc allowed).
// px layout: [dir][t][b][768]   (time-major so each scan step reads one slab)
// y0 layout: [t][b][512]        (row = t*128+b, K-contig for the L1 GEMM)
// ---------------------------------------------------------------------------
__device__ float    g_px0[2 * T_ * B_ * G3];          // 805 MB
__device__ float    g_px1[2 * T_ * B_ * G3];          // 805 MB
__device__ float    g_y0 [T_ * B_ * 2 * H_];          // 268 MB
__device__ float    g_h  [2 * 2 * 2 * B_ * H_];       // [layer][parity][dir][B][H]
__device__ float    g_hlast[2 * B_ * H_];             // [dir][B][H]
__device__ unsigned g_flags[2 * 2 * 8 * T_];          // [layer][dir][bgroup][step]

// ---------------------------------------------------------------------------
// Zero h buffers + sync flags (runs every launch -> graph replays deterministic)
// ---------------------------------------------------------------------------
__global__ void zero_kernel() {
    const int n1 = 2 * 2 * 2 * B_ * H_;
    const int n2 = 2 * 2 * 8 * T_;
    int stride = gridDim.x * blockDim.x;
    for (int i = blockIdx.x * blockDim.x + threadIdx.x; i < n1; i += stride)
        g_h[i] = 0.0f;
    for (int i = blockIdx.x * blockDim.x + threadIdx.x; i < n2; i += stride)
        g_flags[i] = 0u;
}

// ---------------------------------------------------------------------------
// Tensor-core projection GEMM (3xTF32 split -> ~fp32 accuracy).
// out = A[M,K] * W[N,K]^T + bias[N], M = 131072, N = 1536, K in {128, 512}.
// mode 0: A = data, row m = b*T + t   (data is [B][T][IN])
// mode 1: A = y0,   row m = t*B + b   (y0   is [T][B][2H])
// Output scattered to px[dir][t][b][g].
//
// CTA tile 128x128x32, 256 threads = 8 warps (4 M x 2 N), warp tile 32x64.
// A/B staged in SMEM as tf32 hi/lo pairs, padded rows of 36 words so
// fragment loads (bank = 4*group + tig (+8kk)) are conflict-free.
// ---------------------------------------------------------------------------
#define TC_SMEM (4 * 128 * 36 * 4)   // Ah, Al, Bh, Bl : 73728 bytes

__device__ __forceinline__ unsigned f2tf(float x) {
    unsigned r; asm("cvt.rna.tf32.f32 %0, %1;" : "=r"(r) : "f"(x)); return r;
}

__device__ __forceinline__ void mma_tf32(float* c, const unsigned* a, const unsigned* b) {
    asm volatile("mma.sync.aligned.m16n8k8.row.col.f32.tf32.tf32.f32 "
                 "{%0,%1,%2,%3}, {%4,%5,%6,%7}, {%8,%9}, {%0,%1,%2,%3};"
                 : "+f"(c[0]), "+f"(c[1]), "+f"(c[2]), "+f"(c[3])
                 : "r"(a[0]), "r"(a[1]), "r"(a[2]), "r"(a[3]),
                   "r"(b[0]), "r"(b[1]));
}

__device__ __forceinline__ void px_scatter(float v, int m, int n, int mode,
                                           const float* __restrict__ bias,
                                           float* __restrict__ out) {
    int t, b;
    if (mode == 0) { b = m >> 10; t = m & (T_ - 1); }
    else           { t = m >> 7;  b = m & (B_ - 1); }
    int dir = (n >= G3) ? 1 : 0;
    int g   = n - dir * G3;
    out[((dir * T_ + t) * B_ + b) * G3 + g] = v + __ldg(&bias[n]);
}

__global__ __launch_bounds__(256, 1)
void gemm_proj_tc(const float* __restrict__ A, const float* __restrict__ W,
                  const float* __restrict__ bias, float* __restrict__ out,
                  int K, int mode)
{
    extern __shared__ unsigned sm_u[];
    unsigned* Ah = sm_u;
    unsigned* Al = Ah + 128 * 36;
    unsigned* Bh = Al + 128 * 36;
    unsigned* Bl = Bh + 128 * 36;

    const int tid  = threadIdx.x;
    const int n0   = blockIdx.x * 128;   // N-tile fastest: co-resident CTAs share A
    const int m0   = blockIdx.y * 128;
    const int wid  = tid >> 5;
    const int lane = tid & 31;
    const int wm   = (wid & 3) * 32;     // warp M offset in tile
    const int wn   = (wid >> 2) * 64;    // warp N offset in tile
    const int g    = lane >> 2;          // groupID 0..7
    const int tg   = lane & 3;           // threadID_in_group 0..3

    float acc[2][8][4];
#pragma unroll
    for (int mt = 0; mt < 2; mt++)
#pragma unroll
        for (int nt = 0; nt < 8; nt++)
#pragma unroll
            for (int j = 0; j < 4; j++) acc[mt][nt][j] = 0.0f;

    for (int k0 = 0; k0 < K; k0 += 32) {
        // ---- stage A and B tiles as tf32 hi/lo ----
#pragma unroll
        for (int i = 0; i < 4; i++) {
            int e = tid + i * 256;          // 0..1023 over 128 rows x 8 float4
            int r = e >> 3;
            int c = (e & 7) * 4;

            float4 va = *(const float4*)&A[(size_t)(m0 + r) * K + k0 + c];
            unsigned h0 = f2tf(va.x), h1 = f2tf(va.y),
                     h2 = f2tf(va.z), h3 = f2tf(va.w);
            *(uint4*)&Ah[r * 36 + c] = make_uint4(h0, h1, h2, h3);
            *(uint4*)&Al[r * 36 + c] = make_uint4(
                f2tf(va.x - __uint_as_float(h0)),
                f2tf(va.y - __uint_as_float(h1)),
                f2tf(va.z - __uint_as_float(h2)),
                f2tf(va.w - __uint_as_float(h3)));

            float4 vb = *(const float4*)&W[(size_t)(n0 + r) * K + k0 + c];
            unsigned p0 = f2tf(vb.x), p1 = f2tf(vb.y),
                     p2 = f2tf(vb.z), p3 = f2tf(vb.w);
            *(uint4*)&Bh[r * 36 + c] = make_uint4(p0, p1, p2, p3);
            *(uint4*)&Bl[r * 36 + c] = make_uint4(
                f2tf(vb.x - __uint_as_float(p0)),
                f2tf(vb.y - __uint_as_float(p1)),
                f2tf(vb.z - __uint_as_float(p2)),
                f2tf(vb.w - __uint_as_float(p3)));
        }
        __syncthreads();

        // ---- 4 x k8 MMA steps ----
#pragma unroll
        for (int kk = 0; kk < 4; kk++) {
            const int kc = kk * 8 + tg;
            unsigned ah[2][4], al[2][4], bh[8][2], bl[8][2];
#pragma unroll
            for (int mt = 0; mt < 2; mt++) {
                int m = wm + mt * 16;
                ah[mt][0] = Ah[(m + g) * 36 + kc];
                ah[mt][1] = Ah[(m + 8 + g) * 36 + kc];
                ah[mt][2] = Ah[(m + g) * 36 + kc + 4];
                ah[mt][3] = Ah[(m + 8 + g) * 36 + kc + 4];
                al[mt][0] = Al[(m + g) * 36 + kc];
                al[mt][1] = Al[(m + 8 + g) * 36 + kc];
                al[mt][2] = Al[(m + g) * 36 + kc + 4];
                al[mt][3] = Al[(m + 8 + g) * 36 + kc + 4];
            }
#pragma unroll
            for (int nt = 0; nt < 8; nt++) {
                int n = wn + nt * 8;
                bh[nt][0] = Bh[(n + g) * 36 + kc];
                bh[nt][1] = Bh[(n + g) * 36 + kc + 4];
                bl[nt][0] = Bl[(n + g) * 36 + kc];
                bl[nt][1] = Bl[(n + g) * 36 + kc + 4];
            }
#pragma unroll
            for (int mt = 0; mt < 2; mt++)
#pragma unroll
                for (int nt = 0; nt < 8; nt++) {
                    mma_tf32(acc[mt][nt], ah[mt], bh[nt]);  // hi*hi
                    mma_tf32(acc[mt][nt], ah[mt], bl[nt]);  // hi*lo
                    mma_tf32(acc[mt][nt], al[mt], bh[nt]);  // lo*hi
                }
        }
        __syncthreads();
    }

    // ---- epilogue: scatter with bias ----
#pragma unroll
    for (int mt = 0; mt < 2; mt++) {
#pragma unroll
        for (int nt = 0; nt < 8; nt++) {
            int m = m0 + wm + mt * 16 + g;
            int n = n0 + wn + nt * 8 + tg * 2;
            px_scatter(acc[mt][nt][0], m,     n,     mode, bias, out);
            px_scatter(acc[mt][nt][1], m,     n + 1, mode, bias, out);
            px_scatter(acc[mt][nt][2], m + 8, n,     mode, bias, out);
            px_scatter(acc[mt][nt][3], m + 8, n + 1, mode, bias, out);
        }
    }
}

// ---------------------------------------------------------------------------
// GRU scan. Grid (8 bgroups, 8 slices, 2 dirs) = 128 CTAs, 256 threads each.
// Each CTA: 16 batches x 32 hidden units, weight slice (96 rows x 256) in SMEM.
// Per step: ph = h @ Wslice^T + b_hh; gates; h_new; L2 exchange + flag sync.
// ---------------------------------------------------------------------------
#define SCAN_SMEM_FLOATS (96 * 260 + 64 * 68 + 16 * 100 + 96)
#define SCAN_SMEM_BYTES  (SCAN_SMEM_FLOATS * 4)

__global__ void gru_scan(const float* __restrict__ px,     // [2][T][B][768]
                         const float* __restrict__ w_hh,   // [2][768][256]
                         const float* __restrict__ b_hh,   // [2][768]
                         float* __restrict__ hbuf,         // [2 parity][2 dir][B][H]
                         unsigned* __restrict__ flags,     // [2 dir][8][T]
                         float* __restrict__ y_out,        // null or [T][B][2H]
                         float* __restrict__ h_last)       // null or [2][B][H]
{
    extern __shared__ float smem[];
    float* W_s  = smem;                       // [96][260] padded
    float* h_s  = W_s + 96 * 260;             // [64 kq][68] padded, 16 batches x 256 k
    float* ph_s = h_s + 64 * 68;              // [16][100]
    float* bb_s = ph_s + 16 * 100;            // [96]

    const int bg  = blockIdx.x;   // batch group 0..7   (16 batches each)
    const int sl  = blockIdx.y;   // hidden slice 0..7  (32 units each)
    const int dir = blockIdx.z;
    const int tid = threadIdx.x;

    // Load weight slice: local row lr = gate*32 + u  ->  global row gate*256 + sl*32 + u
    const float* wsrc = w_hh + dir * (G3 * H_);
    for (int e = tid; e < 96 * 256; e += 256) {
        int lr = e >> 8, k = e & 255;
        int grow = (lr >> 5) * H_ + sl * 32 + (lr & 31);
        W_s[lr * 260 + k] = wsrc[grow * H_ + k];
    }
    if (tid < 96) {
        int grow = (tid >> 5) * H_ + sl * 32 + (tid & 31);
        bb_s[tid] = b_hh[dir * G3 + grow];
    }
    __syncthreads();

    const int w     = tid >> 5;
    const int l     = tid & 31;
    const int bb    = l & 15;          // batch within group (lane-major -> coalesced h)
    const int half  = l >> 4;
    const int cbase = w * 12 + half * 6;   // 6 output rows per thread, covers 0..95

    for (int step = 0; step < T_; step++) {
        const int t = dir ? (T_ - 1 - step) : step;
        const int p = step & 1;
        const float* hsrc = hbuf + (p * 2 + dir) * (B_ * H_);
        float*       hdst = hbuf + (((p ^ 1) * 2) + dir) * (B_ * H_);

        // Load full h (16 batches x 256) into SMEM, k-major for float4 reads.
        // __ldcg: bypass (incoherent) L1 -- h was written by peer CTAs.
        for (int e = tid; e < 16 * 256; e += 256) {
            int b = e >> 8, k = e & 255;
            h_s[(k >> 2) * 68 + b * 4 + (k & 3)] = __ldcg(&hsrc[(bg * 16 + b) * H_ + k]);
        }
        __syncthreads();

        // ph[bb][cbase..cbase+5] = b_hh + sum_k h[bb][k] * W[c][k]
        float acc[6];
#pragma unroll
        for (int j = 0; j < 6; j++) acc[j] = bb_s[cbase + j];

        const float4* h4 = (const float4*)h_s;
#pragma unroll 8
        for (int kq = 0; kq < 64; kq++) {
            float4 hv = h4[kq * 17 + bb];
#pragma unroll
            for (int j = 0; j < 6; j++) {
                float4 wv = *(const float4*)&W_s[(cbase + j) * 260 + kq * 4];
                acc[j] += hv.x * wv.x;
                acc[j] += hv.y * wv.y;
                acc[j] += hv.z * wv.z;
                acc[j] += hv.w * wv.w;
            }
        }
#pragma unroll
        for (int j = 0; j < 6; j++) ph_s[bb * 100 + cbase + j] = acc[j];
        __syncthreads();

        // Gates + state update: 512 (batch,unit) tasks, 2 per thread.
#pragma unroll
        for (int it = 0; it < 2; it++) {
            int id = tid + it * 256;
            int b  = id >> 5, u = id & 31;
            int bglob = bg * 16 + b;
            int ug    = sl * 32 + u;
            const float* pxr = px + ((dir * T_ + t) * B_ + bglob) * G3;
            float xr = pxr[ug], xz = pxr[H_ + ug], xn = pxr[2 * H_ + ug];
            float hr = ph_s[b * 100 + u];
            float hz = ph_s[b * 100 + 32 + u];
            float hn = ph_s[b * 100 + 64 + u];
            float r = 1.0f / (1.0f + __expf(-(xr + hr)));
            float z = 1.0f / (1.0f + __expf(-(xz + hz)));
            float n = tanhf(xn + r * hn);
            float hp = h_s[(ug >> 2) * 68 + b * 4 + (ug & 3)];
            float hnew = (1.0f - z) * n + z * hp;
            __stcg(&hdst[bglob * H_ + ug], hnew);
            if (y_out)
                y_out[(t * B_ + bglob) * (2 * H_) + dir * H_ + ug] = hnew;
            if (h_last && step == T_ - 1)
                h_last[(dir * B_ + bglob) * H_ + ug] = hnew;
        }

        // Publish + wait for the 7 sibling slice-CTAs of this (dir, bgroup).
        __threadfence();
        __syncthreads();
        unsigned* f = flags + (dir * 8 + bg) * T_ + step;
        if (tid == 0) {
            atomicAdd(f, 1u);
            while (*(volatile unsigned*)f < 8u) { }
        }
        __syncthreads();
    }
}

// ---------------------------------------------------------------------------
// Output head: out[b][o] = concat(hf[b], hb[b]) . w_out[o] + b_out[o]
// ---------------------------------------------------------------------------
__global__ void head_kernel(const float* __restrict__ hlast,   // [2][B][H]
                            const float* __restrict__ w_out,   // [4][512]
                            const float* __restrict__ b_out,   // [4]
                            float* __restrict__ out)           // [B][4]
{
    int id = blockIdx.x * blockDim.x + threadIdx.x;
    if (id >= B_ * NOUT) return;
    int b = id >> 2, o = id & 3;
    const float* hf = hlast + b * H_;
    const float* hb = hlast + (B_ + b) * H_;
    const float* wo = w_out + o * (2 * H_);
    float s = b_out[o];
#pragma unroll 8
    for (int j = 0; j < H_; j++) s += hf[j] * wo[j];
#pragma unroll 8
    for (int j = 0; j < H_; j++) s += hb[j] * wo[H_ + j];
    out[id] = s;
}

// ---------------------------------------------------------------------------
// Launch
// ---------------------------------------------------------------------------
extern "C" void kernel_launch(void* const* d_in, const int* in_sizes, int n_in,
                              void* d_out, int out_size)
{
    const float* data  = (const float*)d_in[0];
    const float* w_ih0 = (const float*)d_in[1];
    const float* w_hh0 = (const float*)d_in[2];
    const float* b_ih0 = (const float*)d_in[3];
    const float* b_hh0 = (const float*)d_in[4];
    const float* w_ih1 = (const float*)d_in[5];
    const float* w_hh1 = (const float*)d_in[6];
    const float* b_ih1 = (const float*)d_in[7];
    const float* b_hh1 = (const float*)d_in[8];
    const float* w_out = (const float*)d_in[9];
    const float* b_out = (const float*)d_in[10];
    float* out = (float*)d_out;

    float *px0, *px1, *y0, *h, *hlast; unsigned* fl;
    cudaGetSymbolAddress((void**)&px0,   g_px0);
    cudaGetSymbolAddress((void**)&px1,   g_px1);
    cudaGetSymbolAddress((void**)&y0,    g_y0);
    cudaGetSymbolAddress((void**)&h,     g_h);
    cudaGetSymbolAddress((void**)&hlast, g_hlast);
    cudaGetSymbolAddress((void**)&fl,    g_flags);

    cudaFuncSetAttribute(gru_scan, cudaFuncAttributeMaxDynamicSharedMemorySize,
                         SCAN_SMEM_BYTES);
    cudaFuncSetAttribute(gemm_proj_tc, cudaFuncAttributeMaxDynamicSharedMemorySize,
                         TC_SMEM);

    zero_kernel<<<256, 256>>>();

    // Layer 0 input projection: M = B*T = 131072, K = 128
    dim3 gtc(1536 / 128, 131072 / 128);   // N-tiles fastest -> A-tile sharing in L2
    gemm_proj_tc<<<gtc, 256, TC_SMEM>>>(data, w_ih0, b_ih0, px0, IN_, 0);

    // Layer 0 bidirectional scan (writes y0)
    dim3 gs(8, 8, 2);
    const int hLayerStride = 2 * 2 * B_ * H_;
    const int fLayerStride = 2 * 8 * T_;
    gru_scan<<<gs, 256, SCAN_SMEM_BYTES>>>(px0, w_hh0, b_hh0,
                                           h, fl, y0, nullptr);

    // Layer 1 input projection: M = T*B = 131072, K = 512
    gemm_proj_tc<<<gtc, 256, TC_SMEM>>>(y0, w_ih1, b_ih1, px1, 2 * H_, 1);

    // Layer 1 bidirectional scan (writes h_last only)
    gru_scan<<<gs, 256, SCAN_SMEM_BYTES>>>(px1, w_hh1, b_hh1,
                                           h + hLayerStride, fl + fLayerStride,
                                           nullptr, hlast);

    // Output head
    head_kernel<<<2, 256>>>(hlast, w_out, b_out, out);
}